// round 6
// baseline (speedup 1.0000x reference)
#include <cuda_runtime.h>
#include <cstdint>

#define NB 4
#define NUM_OP 6
#define LANG_DIM 256
#define NHIDDEN 128
#define HH 128
#define WW 128
#define HWSZ (HH * WW)        // 16384
#define NC 128
#define SEM_CH (NUM_OP + 2)   // 8

#define CCHUNK 8
#define TPB 256
#define GRID_X (HWSZ / 4 / TPB)     // 16
#define GRID_Z (NC / CCHUNK)        // 16
#define TOTAL_BLOCKS (GRID_X * NB * GRID_Z)  // 1024
#define N_PROD 32                   // producer blocks for the actv GEMV

// Coefficient scratch + sync state (zero-initialized at module load; the
// kernel restores all counters/flags to 0 before exiting -> replay-safe).
__device__ float4 g_actv4[NB][NHIDDEN / 4];
__device__ float  g_gw[NB][NUM_OP];
__device__ float  g_bw[NB][NUM_OP];
__device__ float  g_wrsum;
__device__ float  g_br;
__device__ int    g_actv_done;
__device__ int    g_flag;
__device__ int    g_done;

__device__ __forceinline__ float dot4(float4 a, float4 b) {
    return a.x * b.x + a.y * b.y + a.z * b.z + a.w * b.w;
}

__device__ __forceinline__ void cp_async16(void* smem_dst, const void* gmem_src) {
    uint32_t s = (uint32_t)__cvta_generic_to_shared(smem_dst);
    asm volatile("cp.async.cg.shared.global [%0], [%1], 16;\n" :: "r"(s), "l"(gmem_src));
}

__global__ __launch_bounds__(TPB, 8) void fused_kernel(
    const float* __restrict__ x,
    const float* __restrict__ lang,
    const float* __restrict__ sem,
    const float* __restrict__ Ws, const float* __restrict__ bs,
    const float* __restrict__ Wg, const float* __restrict__ bg,
    const float* __restrict__ Wb, const float* __restrict__ bb,
    const float* __restrict__ Wr, const float* __restrict__ br,
    float* __restrict__ out) {
    const int tid  = threadIdx.x;
    const int warp = tid >> 5;
    const int lane = tid & 31;
    const int b    = blockIdx.y;
    const int c0   = blockIdx.z * CCHUNK;
    const int hw4  = blockIdx.x * TPB + tid;
    const int fb   = blockIdx.x + GRID_X * (blockIdx.y + NB * blockIdx.z);

    __shared__ float4 s_sem[NUM_OP][TPB];

    // ---------------- Producer phase: blocks 0..31 build actv ----------------
    if (fb < N_PROD) {
        // warp w: row n = 4*fb + (w>>1), batches b0 = (w&1)*2 .. +1
        const int n  = 4 * fb + (warp >> 1);
        const int b0 = (warp & 1) * 2;
        const float4* Ws4   = reinterpret_cast<const float4*>(Ws) + (size_t)n * (LANG_DIM / 4);
        const float4* lang4 = reinterpret_cast<const float4*>(lang);

        float p0 = 0.0f, p1 = 0.0f;
#pragma unroll
        for (int i = 0; i < 2; ++i) {
            const int idx = lane + 32 * i;
            const float4 wv = Ws4[idx];
            p0 += dot4(wv, lang4[(size_t)b0 * (LANG_DIM / 4) + idx]);
            p1 += dot4(wv, lang4[(size_t)(b0 + 1) * (LANG_DIM / 4) + idx]);
        }
#pragma unroll
        for (int off = 16; off > 0; off >>= 1) {
            p0 += __shfl_xor_sync(0xFFFFFFFFu, p0, off);
            p1 += __shfl_xor_sync(0xFFFFFFFFu, p1, off);
        }
        if (lane == 0) {
            const float bias = bs[n];
            reinterpret_cast<float*>(g_actv4[b0])[n]     = p0 + bias;
            reinterpret_cast<float*>(g_actv4[b0 + 1])[n] = p1 + bias;
        }
        __syncthreads();
        if (tid == 0) {
            __threadfence();
            atomicAdd(&g_actv_done, 1);
        }
    }

    // ---------------- Fold phase: block 0 publishes coefficients -------------
    if (fb == 0) {
        if (tid == 0) {
            volatile int* vd = &g_actv_done;
            while (*vd < N_PROD) __nanosleep(32);
            __threadfence();
        }
        __syncthreads();

        if (warp < NUM_OP) {
            const int k = warp;
            const float4 wg = reinterpret_cast<const float4*>(Wg)[(size_t)k * (NHIDDEN / 4) + lane];
            const float4 wb = reinterpret_cast<const float4*>(Wb)[(size_t)k * (NHIDDEN / 4) + lane];
            float pg[NB], pb[NB];
#pragma unroll
            for (int bb2 = 0; bb2 < NB; ++bb2) {
                const float4 a = g_actv4[bb2][lane];
                pg[bb2] = dot4(a, wg);
                pb[bb2] = dot4(a, wb);
            }
#pragma unroll
            for (int off = 16; off > 0; off >>= 1)
#pragma unroll
                for (int bb2 = 0; bb2 < NB; ++bb2) {
                    pg[bb2] += __shfl_xor_sync(0xFFFFFFFFu, pg[bb2], off);
                    pb[bb2] += __shfl_xor_sync(0xFFFFFFFFu, pb[bb2], off);
                }
            if (lane == 0) {
                const float wr = Wr[k];
#pragma unroll
                for (int bb2 = 0; bb2 < NB; ++bb2) {
                    g_gw[bb2][k] = (pg[bb2] + bg[k]) * wr;
                    g_bw[bb2][k] = (pb[bb2] + bb[k]) * wr;
                }
            }
        } else if (warp == 6 && lane == 0) {
            float s = 0.0f;
#pragma unroll
            for (int k = 0; k < NUM_OP; ++k) s += Wr[k];
            g_wrsum = s;
            g_br = br[0];
        }
        __syncthreads();
        if (tid == 0) {
            __threadfence();
            atomicExch(&g_flag, 1);
        }
    }

    // ---------------- Consumer phase: all 1024 blocks ------------------------
    // 1) Prefetch the 6 semantic tiles into smem (overlaps the flag wait).
    const float4* semb =
        reinterpret_cast<const float4*>(sem + (size_t)b * SEM_CH * HWSZ + 2 * HWSZ) + hw4;
#pragma unroll
    for (int k = 0; k < NUM_OP; ++k)
        cp_async16(&s_sem[k][tid], semb + (size_t)k * (HWSZ / 4));
    asm volatile("cp.async.commit_group;\n");

    // 2) Wait for coefficients.
    if (tid == 0) {
        volatile int* vf = &g_flag;
        while (*vf == 0) __nanosleep(64);
        __threadfence();
    }
    __syncthreads();

    // 3) Fold scale/shift.
    float4 scale = make_float4(g_wrsum, g_wrsum, g_wrsum, g_wrsum);
    float4 shift = make_float4(g_br, g_br, g_br, g_br);
    asm volatile("cp.async.wait_group 0;\n");
#pragma unroll
    for (int k = 0; k < NUM_OP; ++k) {
        const float gw = g_gw[b][k];
        const float bw = g_bw[b][k];
        const float4 s = s_sem[k][tid];
        scale.x += gw * s.x;  scale.y += gw * s.y;
        scale.z += gw * s.z;  scale.w += gw * s.w;
        shift.x += bw * s.x;  shift.y += bw * s.y;
        shift.z += bw * s.z;  shift.w += bw * s.w;
    }

    // 4) Stream 8 channels of x -> out.
    const float4* xb = reinterpret_cast<const float4*>(x + (size_t)b * NC * HWSZ) + hw4;
    float4*       ob = reinterpret_cast<float4*>(out + (size_t)b * NC * HWSZ) + hw4;
#pragma unroll
    for (int c = c0; c < c0 + CCHUNK; ++c) {
        const float4 xv = xb[(size_t)c * (HWSZ / 4)];
        float4 o;
        o.x = xv.x * scale.x + shift.x;
        o.y = xv.y * scale.y + shift.y;
        o.z = xv.z * scale.z + shift.z;
        o.w = xv.w * scale.w + shift.w;
        ob[(size_t)c * (HWSZ / 4)] = o;
    }

    // 5) Last block resets sync state for the next graph replay.
    __syncthreads();
    if (tid == 0) {
        const int n = atomicAdd(&g_done, 1);
        if (n == TOTAL_BLOCKS - 1) {
            g_actv_done = 0;
            g_flag = 0;
            g_done = 0;
            __threadfence();
        }
    }
}

// ---------------------------------------------------------------------------
extern "C" void kernel_launch(void* const* d_in, const int* in_sizes, int n_in,
                              void* d_out, int out_size) {
    const float* x    = (const float*)d_in[0];
    const float* lang = (const float*)d_in[1];
    const float* sem  = (const float*)d_in[2];
    const float* Ws   = (const float*)d_in[3];
    const float* bs   = (const float*)d_in[4];
    const float* Wg   = (const float*)d_in[5];
    const float* bg   = (const float*)d_in[6];
    const float* Wb   = (const float*)d_in[7];
    const float* bb   = (const float*)d_in[8];
    const float* Wr   = (const float*)d_in[9];
    const float* br   = (const float*)d_in[10];
    float* out = (float*)d_out;

    dim3 grid(GRID_X, NB, GRID_Z);
    fused_kernel<<<grid, TPB>>>(x, lang, sem, Ws, bs, Wg, bg, Wb, bb, Wr, br, out);
}

// round 7
// speedup vs baseline: 1.1911x; 1.1911x over previous
#include <cuda_runtime.h>
#include <cstdint>

#define NB 4
#define NUM_OP 6
#define LANG_DIM 256
#define NHIDDEN 128
#define HH 128
#define WW 128
#define HWSZ (HH * WW)        // 16384
#define NC 128
#define SEM_CH (NUM_OP + 2)   // 8

#define CCHUNK 16
#define TPB 256
#define GRID_X (HWSZ / 4 / TPB)     // 16
#define GRID_Z (NC / CCHUNK)        // 8   -> 16*4*8 = 512 blocks

// actv[b][n] produced by K1, consumed (redundantly) by every K2 block.
__device__ float4 g_actv4[NB][NHIDDEN / 4];

__device__ __forceinline__ float dot4(float4 a, float4 b) {
    return a.x * b.x + a.y * b.y + a.z * b.z + a.w * b.w;
}

__device__ __forceinline__ void cp_async16(void* smem_dst, const void* gmem_src) {
    uint32_t s = (uint32_t)__cvta_generic_to_shared(smem_dst);
    asm volatile("cp.async.cg.shared.global [%0], [%1], 16;\n" :: "r"(s), "l"(gmem_src));
}

// ---------------------------------------------------------------------------
// K1: actv[b][n] = bs[n] + lang[b,:].Ws[n,:]  — 32 blocks x 256 threads.
// Block q, warp w: row n = 4q + (w>>1), batch pair b0 = (w&1)*2.
// Each block reads 4 KB of Ws, fully coalesced; Ws read once chip-wide.
// ---------------------------------------------------------------------------
__global__ __launch_bounds__(TPB) void actv_kernel(
    const float* __restrict__ lang,
    const float* __restrict__ Ws, const float* __restrict__ bs) {
    const int warp = threadIdx.x >> 5;
    const int lane = threadIdx.x & 31;
    const int n  = 4 * blockIdx.x + (warp >> 1);
    const int b0 = (warp & 1) * 2;

    const float4* Ws4   = reinterpret_cast<const float4*>(Ws) + (size_t)n * (LANG_DIM / 4);
    const float4* lang4 = reinterpret_cast<const float4*>(lang);

    float p0 = 0.0f, p1 = 0.0f;
#pragma unroll
    for (int i = 0; i < 2; ++i) {
        const int idx = lane + 32 * i;
        const float4 wv = Ws4[idx];
        p0 += dot4(wv, lang4[(size_t)b0 * (LANG_DIM / 4) + idx]);
        p1 += dot4(wv, lang4[(size_t)(b0 + 1) * (LANG_DIM / 4) + idx]);
    }
#pragma unroll
    for (int off = 16; off > 0; off >>= 1) {
        p0 += __shfl_xor_sync(0xFFFFFFFFu, p0, off);
        p1 += __shfl_xor_sync(0xFFFFFFFFu, p1, off);
    }
    if (lane == 0) {
        const float bias = bs[n];
        reinterpret_cast<float*>(g_actv4[b0])[n]     = p0 + bias;
        reinterpret_cast<float*>(g_actv4[b0 + 1])[n] = p1 + bias;
    }
}

// ---------------------------------------------------------------------------
// K2: each block derives its own gw/bw coefficients (warps 0-6, L2-hot reads,
// overlapped with cp.async sem prefetch), then streams 16 channels of x.
// Grid (16,4,8) = 512 blocks x 256 threads, 4 blocks/SM -> one wave.
// ---------------------------------------------------------------------------
__global__ __launch_bounds__(TPB, 4) void main_kernel(
    const float* __restrict__ x,
    const float* __restrict__ sem,
    const float* __restrict__ Wg, const float* __restrict__ bg,
    const float* __restrict__ Wb, const float* __restrict__ bb,
    const float* __restrict__ Wr, const float* __restrict__ br,
    float* __restrict__ out) {
    const int tid  = threadIdx.x;
    const int warp = tid >> 5;
    const int lane = tid & 31;
    const int b    = blockIdx.y;
    const int c0   = blockIdx.z * CCHUNK;
    const int hw4  = blockIdx.x * TPB + tid;

    __shared__ float4 s_sem[NUM_OP][TPB];          // 24 KB
    __shared__ float  s_gw[NUM_OP], s_bw[NUM_OP];
    __shared__ float  s_wrsum, s_br;

    // 1) Prefetch the 6 semantic tiles into smem (async, overlaps prologue).
    const float4* semb =
        reinterpret_cast<const float4*>(sem + (size_t)b * SEM_CH * HWSZ + 2 * HWSZ) + hw4;
#pragma unroll
    for (int k = 0; k < NUM_OP; ++k)
        cp_async16(&s_sem[k][tid], semb + (size_t)k * (HWSZ / 4));
    asm volatile("cp.async.commit_group;\n");

    // 2) Per-block coefficient fold (redundant across blocks; all L2-hot).
    if (warp < NUM_OP) {
        const int k = warp;
        const float4 a  = g_actv4[b][lane];
        const float4 wg = reinterpret_cast<const float4*>(Wg)[(size_t)k * (NHIDDEN / 4) + lane];
        const float4 wb = reinterpret_cast<const float4*>(Wb)[(size_t)k * (NHIDDEN / 4) + lane];
        float pg = dot4(a, wg);
        float pb = dot4(a, wb);
#pragma unroll
        for (int off = 16; off > 0; off >>= 1) {
            pg += __shfl_xor_sync(0xFFFFFFFFu, pg, off);
            pb += __shfl_xor_sync(0xFFFFFFFFu, pb, off);
        }
        if (lane == 0) {
            const float wr = Wr[k];
            s_gw[k] = (pg + bg[k]) * wr;
            s_bw[k] = (pb + bb[k]) * wr;
        }
    } else if (warp == 6 && lane == 0) {
        float s = 0.0f;
#pragma unroll
        for (int k = 0; k < NUM_OP; ++k) s += Wr[k];
        s_wrsum = s;
        s_br = br[0];
    }
    __syncthreads();

    // 3) Fold scale/shift from smem sem tiles.
    float4 scale = make_float4(s_wrsum, s_wrsum, s_wrsum, s_wrsum);
    float4 shift = make_float4(s_br, s_br, s_br, s_br);
    asm volatile("cp.async.wait_group 0;\n");
    __syncthreads();
#pragma unroll
    for (int k = 0; k < NUM_OP; ++k) {
        const float gw = s_gw[k];
        const float bw = s_bw[k];
        const float4 s = s_sem[k][tid];
        scale.x += gw * s.x;  scale.y += gw * s.y;
        scale.z += gw * s.z;  scale.w += gw * s.w;
        shift.x += bw * s.x;  shift.y += bw * s.y;
        shift.z += bw * s.z;  shift.w += bw * s.w;
    }

    // 4) Stream 16 channels of x -> out.
    const float4* xb = reinterpret_cast<const float4*>(x + (size_t)b * NC * HWSZ) + hw4;
    float4*       ob = reinterpret_cast<float4*>(out + (size_t)b * NC * HWSZ) + hw4;
#pragma unroll 8
    for (int c = c0; c < c0 + CCHUNK; ++c) {
        const float4 xv = xb[(size_t)c * (HWSZ / 4)];
        float4 o;
        o.x = xv.x * scale.x + shift.x;
        o.y = xv.y * scale.y + shift.y;
        o.z = xv.z * scale.z + shift.z;
        o.w = xv.w * scale.w + shift.w;
        ob[(size_t)c * (HWSZ / 4)] = o;
    }
}

// ---------------------------------------------------------------------------
extern "C" void kernel_launch(void* const* d_in, const int* in_sizes, int n_in,
                              void* d_out, int out_size) {
    const float* x    = (const float*)d_in[0];
    const float* lang = (const float*)d_in[1];
    const float* sem  = (const float*)d_in[2];
    const float* Ws   = (const float*)d_in[3];
    const float* bs   = (const float*)d_in[4];
    const float* Wg   = (const float*)d_in[5];
    const float* bg   = (const float*)d_in[6];
    const float* Wb   = (const float*)d_in[7];
    const float* bb   = (const float*)d_in[8];
    const float* Wr   = (const float*)d_in[9];
    const float* br   = (const float*)d_in[10];
    float* out = (float*)d_out;

    actv_kernel<<<32, TPB>>>(lang, Ws, bs);

    dim3 grid(GRID_X, NB, GRID_Z);
    main_kernel<<<grid, TPB>>>(x, sem, Wg, bg, Wb, bb, Wr, br, out);
}